// round 2
// baseline (speedup 1.0000x reference)
#include <cuda_runtime.h>

// ts_cov: sliding-window pairwise covariance.
// x: [B=256, T=512, F=32] f32 -> out: [B, S=508, C=496] f32
// cov[b,s,c(i,j)] = mean_{t in [s,s+5)}(x_i x_j) - mean(x_i)*mean(x_j)

#define B_DIM 256
#define T_DIM 512
#define F_DIM 32
#define W 5
#define S_DIM (T_DIM - W + 1)          // 508 (tail start 507 already in range)
#define C_DIM (F_DIM * (F_DIM - 1) / 2) // 496
#define S_TILE 16
#define ROWS (S_TILE + W - 1)          // 20
#define NTHREADS 512
#define TILES_PER_B ((S_DIM + S_TILE - 1) / S_TILE) // 32

__global__ __launch_bounds__(NTHREADS)
void ts_cov_kernel(const float* __restrict__ x, float* __restrict__ out) {
    __shared__ float sx[ROWS][F_DIM];   // staged x rows
    __shared__ float sa[S_TILE][F_DIM]; // window means

    const int blk  = blockIdx.x;
    const int b    = blk / TILES_PER_B;
    const int tile = blk % TILES_PER_B;
    const int s0   = tile * S_TILE;
    const int s_cnt = min(S_TILE, S_DIM - s0);   // 16, or 12 on the last tile
    const int rows  = s_cnt + W - 1;             // rows to load (s0+rows <= T always)

    const int tid = threadIdx.x;

    // ---- Stage x[b, s0 : s0+rows, :] into smem (one contiguous span) ----
    const float* gx = x + ((long)b * T_DIM + s0) * F_DIM;
    const int nelem = rows * F_DIM;
    for (int idx = tid; idx < nelem; idx += NTHREADS)
        ((float*)sx)[idx] = gx[idx];
    __syncthreads();

    // ---- Window means: one (s_local, f) per thread ----
    if (tid < s_cnt * F_DIM) {
        const int sl = tid >> 5;
        const int f  = tid & 31;
        float s = ((sx[sl][f] + sx[sl + 1][f]) + (sx[sl + 2][f] + sx[sl + 3][f]))
                  + sx[sl + 4][f];
        sa[sl][f] = s * (1.0f / W);
    }
    __syncthreads();

    if (tid >= C_DIM) return;
    const int c = tid;

    // ---- Decode pair index c -> (i, j), matching triu_indices(F, k=1) order ----
    int i = 0, rem = c;
    while (rem >= (F_DIM - 1 - i)) { rem -= (F_DIM - 1 - i); ++i; }
    const int j = i + 1 + rem;

    // ---- Stage the two feature columns into registers ----
    float xi[ROWS], xj[ROWS];
    #pragma unroll
    for (int r = 0; r < ROWS; ++r) { xi[r] = sx[r][i]; xj[r] = sx[r][j]; }
    // (rows beyond 'rows' hold garbage on partial tiles; only used in
    //  iterations whose stores are predicated off.)

    // ---- Sliding product ring ----
    float p[W];
    #pragma unroll
    for (int t = 0; t < W; ++t) p[t] = xi[t] * xj[t];
    float sp = ((p[0] + p[1]) + (p[2] + p[3])) + p[4];

    float* o = out + ((long)b * S_DIM + s0) * C_DIM + c;

    #pragma unroll
    for (int sl = 0; sl < S_TILE; ++sl) {
        if (sl < s_cnt) {
            const float cov = fmaf(sp, 1.0f / W, -(sa[sl][i] * sa[sl][j]));
            o[(long)sl * C_DIM] = cov;
        }
        if (sl + 1 < S_TILE) {
            const float pn = xi[sl + W] * xj[sl + W];
            sp += pn - p[sl % W];
            p[sl % W] = pn;
        }
    }
}

extern "C" void kernel_launch(void* const* d_in, const int* in_sizes, int n_in,
                              void* d_out, int out_size) {
    const float* x = (const float*)d_in[0];
    float* out = (float*)d_out;
    (void)in_sizes; (void)n_in; (void)out_size;
    dim3 grid(B_DIM * TILES_PER_B);
    ts_cov_kernel<<<grid, NTHREADS>>>(x, out);
}

// round 3
// speedup vs baseline: 1.1440x; 1.1440x over previous
#include <cuda_runtime.h>

// ts_cov: sliding-window pairwise covariance.
// x: [B=256, T=512, F=32] f32 -> out: [B, S=508, C=496] f32
// cov[b,s,c(i,j)] = mean_{t in [s,s+5)}(x_i x_j) - mean(x_i)*mean(x_j)

#define B_DIM 256
#define T_DIM 512
#define F_DIM 32
#define W 5
#define S_DIM (T_DIM - W + 1)            // 508
#define C_DIM (F_DIM * (F_DIM - 1) / 2)  // 496
#define S_TILE 16
#define ROWS (S_TILE + W - 1)            // 20
#define NTHREADS 512
#define TILES_PER_B ((S_DIM + S_TILE - 1) / S_TILE) // 32

__global__ __launch_bounds__(NTHREADS)
void ts_cov_kernel(const float* __restrict__ x, float* __restrict__ out) {
    __shared__ float sx[ROWS][F_DIM];

    const int b     = blockIdx.y;
    const int s0    = blockIdx.x * S_TILE;
    const int s_cnt = min(S_TILE, S_DIM - s0);   // 16, or 12 on last tile
    const int rows  = s_cnt + W - 1;
    const int tid   = threadIdx.x;

    // ---- Stage x[b, s0 : s0+rows, :] into smem (contiguous, coalesced) ----
    const float* gx = x + ((long)b * T_DIM + s0) * F_DIM;
    const int nelem = rows * F_DIM;
    for (int idx = tid; idx < nelem; idx += NTHREADS)
        ((float*)sx)[idx] = gx[idx];
    __syncthreads();

    if (tid >= C_DIM) return;
    const int c = tid;

    // ---- Closed-form pair decode c -> (i, j), triu_indices(F, k=1) order ----
    // off(i) = i*(2F-1-i)/2 ; i = floor((2F-1 - sqrt((2F-1)^2 - 8c)) / 2)
    const int TF = 2 * F_DIM - 1; // 63
    float disc = (float)(TF * TF - 8 * c);
    int i = (int)(((float)TF - sqrtf(disc)) * 0.5f);
    int off = (i * (TF - i)) >> 1;
    if (c < off)                      { --i; off = (i * (TF - i)) >> 1; }
    else if (c >= off + (F_DIM - 1 - i)) { ++i; off = (i * (TF - i)) >> 1; }
    const int j = c - off + i + 1;

    // ---- Init sliding rings over the first window ----
    float xi_r[W], xj_r[W], p_r[W];
    float si = 0.f, sj = 0.f, sp = 0.f;
    #pragma unroll
    for (int t = 0; t < W; ++t) {
        const float a = sx[t][i];
        const float v = sx[t][j];
        const float p = a * v;
        xi_r[t] = a; xj_r[t] = v; p_r[t] = p;
        si += a; sj += v; sp += p;
    }

    float* o = out + ((long)b * S_DIM + s0) * C_DIM + c;
    const float inv  = 1.0f / W;        // 0.2
    const float inv2 = 1.0f / (W * W);  // 0.04

    if (s_cnt == S_TILE) {
        // ---- Full tile: no predicates, fully unrolled ----
        #pragma unroll
        for (int sl = 0; sl < S_TILE; ++sl) {
            const float cov = fmaf(sp, inv, -(si * sj) * inv2);
            o[(long)sl * C_DIM] = cov;
            if (sl + 1 < S_TILE) {
                const float xn = sx[sl + W][i];
                const float yn = sx[sl + W][j];
                const float pn = xn * yn;
                const int k = sl % W;
                sp += pn - p_r[k];
                si += xn - xi_r[k];
                sj += yn - xj_r[k];
                xi_r[k] = xn; xj_r[k] = yn; p_r[k] = pn;
            }
        }
    } else {
        // ---- Partial tail tile (s_cnt = 12) ----
        #pragma unroll
        for (int sl = 0; sl < S_TILE; ++sl) {
            if (sl < s_cnt) {
                const float cov = fmaf(sp, inv, -(si * sj) * inv2);
                o[(long)sl * C_DIM] = cov;
            }
            if (sl + 1 < s_cnt) {
                const float xn = sx[sl + W][i];
                const float yn = sx[sl + W][j];
                const float pn = xn * yn;
                const int k = sl % W;
                sp += pn - p_r[k];
                si += xn - xi_r[k];
                sj += yn - xj_r[k];
                xi_r[k] = xn; xj_r[k] = yn; p_r[k] = pn;
            }
        }
    }
}

extern "C" void kernel_launch(void* const* d_in, const int* in_sizes, int n_in,
                              void* d_out, int out_size) {
    const float* x = (const float*)d_in[0];
    float* out = (float*)d_out;
    (void)in_sizes; (void)n_in; (void)out_size;
    dim3 grid(TILES_PER_B, B_DIM);
    ts_cov_kernel<<<grid, NTHREADS>>>(x, out);
}

// round 4
// speedup vs baseline: 1.4316x; 1.2514x over previous
#include <cuda_runtime.h>

// ts_cov: sliding-window pairwise covariance.
// x: [B=256, T=512, F=32] f32 -> out: [B, S=508, C=496] f32
// cov[b,s,c(i,j)] = mean_{t in [s,s+5)}(x_i x_j) - mean(x_i)*mean(x_j)
// Each thread owns TWO pairs (c = tid, c = tid + 248) and advances both
// sliding windows with packed f32x2 arithmetic (sm_103a).

#define B_DIM 256
#define T_DIM 512
#define F_DIM 32
#define W 5
#define S_DIM (T_DIM - W + 1)            // 508
#define C_DIM (F_DIM * (F_DIM - 1) / 2)  // 496
#define HALF_C (C_DIM / 2)               // 248
#define S_TILE 32
#define ROWS (S_TILE + W - 1)            // 36
#define NTHREADS 256
#define TILES_PER_B ((S_DIM + S_TILE - 1) / S_TILE) // 16

typedef unsigned long long u64;

// ---- packed f32x2 helpers (Blackwell; ptxas never auto-fuses these) ----
__device__ __forceinline__ u64 pack2(float lo, float hi) {
    u64 r;
    asm("mov.b64 %0, {%1, %2};" : "=l"(r) : "r"(__float_as_uint(lo)), "r"(__float_as_uint(hi)));
    return r;
}
__device__ __forceinline__ void unpack2(u64 v, float& lo, float& hi) {
    unsigned a, b;
    asm("mov.b64 {%0, %1}, %2;" : "=r"(a), "=r"(b) : "l"(v));
    lo = __uint_as_float(a); hi = __uint_as_float(b);
}
__device__ __forceinline__ u64 mul2(u64 a, u64 b) {
    u64 r; asm("mul.rn.f32x2 %0, %1, %2;" : "=l"(r) : "l"(a), "l"(b)); return r;
}
__device__ __forceinline__ u64 add2(u64 a, u64 b) {
    u64 r; asm("add.rn.f32x2 %0, %1, %2;" : "=l"(r) : "l"(a), "l"(b)); return r;
}
__device__ __forceinline__ u64 sub2(u64 a, u64 b) {
    u64 r; asm("sub.rn.f32x2 %0, %1, %2;" : "=l"(r) : "l"(a), "l"(b)); return r;
}
__device__ __forceinline__ u64 fma2(u64 a, u64 b, u64 c) {
    u64 r; asm("fma.rn.f32x2 %0, %1, %2, %3;" : "=l"(r) : "l"(a), "l"(b), "l"(c)); return r;
}

// ---- closed-form pair decode c -> (i, j), triu_indices(F, k=1) order ----
__device__ __forceinline__ void decode_pair(int c, int& io, int& jo) {
    const int TF = 2 * F_DIM - 1; // 63
    float disc = (float)(TF * TF - 8 * c);
    int i = (int)(((float)TF - sqrtf(disc)) * 0.5f);
    int off = (i * (TF - i)) >> 1;
    if (c < off)                          { --i; off = (i * (TF - i)) >> 1; }
    else if (c >= off + (F_DIM - 1 - i))  { ++i; off = (i * (TF - i)) >> 1; }
    io = i; jo = c - off + i + 1;
}

__global__ __launch_bounds__(NTHREADS)
void ts_cov_kernel(const float* __restrict__ x, float* __restrict__ out) {
    __shared__ float sx[ROWS][F_DIM];

    const int b     = blockIdx.y;
    const int s0    = blockIdx.x * S_TILE;
    const int s_cnt = min(S_TILE, S_DIM - s0);   // 32, or 28 on last tile
    const int rows  = s_cnt + W - 1;
    const int tid   = threadIdx.x;

    // ---- Stage x[b, s0 : s0+rows, :] into smem (float4, coalesced) ----
    const float4* gx = (const float4*)(x + ((long)b * T_DIM + s0) * F_DIM);
    const int nv = rows * (F_DIM / 4);
    for (int idx = tid; idx < nv; idx += NTHREADS)
        ((float4*)sx)[idx] = gx[idx];
    __syncthreads();

    if (tid >= HALF_C) return;

    int iA, jA, iB, jB;
    decode_pair(tid, iA, jA);
    decode_pair(tid + HALF_C, iB, jB);

    const u64 INVP = pack2(0.2f, 0.2f);     //  1/W
    const u64 NI25 = pack2(-0.04f, -0.04f); // -1/W^2

    // ---- Init sliding rings (x, y values; products recomputed on exit) ----
    u64 xr[W], yr[W];
    u64 s2x = 0ull, s2y = 0ull, s2p = 0ull; // bit pattern 0 == (0.f, 0.f)
    #pragma unroll
    for (int t = 0; t < W; ++t) {
        u64 x2 = pack2(sx[t][iA], sx[t][iB]);
        u64 y2 = pack2(sx[t][jA], sx[t][jB]);
        u64 p2 = mul2(x2, y2);
        xr[t] = x2; yr[t] = y2;
        s2x = add2(s2x, x2); s2y = add2(s2y, y2); s2p = add2(s2p, p2);
    }

    float* oA = out + ((long)b * S_DIM + s0) * C_DIM + tid;

    if (s_cnt == S_TILE) {
        // ---- Full tile: fully unrolled, no predicates ----
        #pragma unroll
        for (int sl = 0; sl < S_TILE; ++sl) {
            u64 m2   = mul2(s2x, s2y);
            u64 a2   = mul2(s2p, INVP);
            u64 cov2 = fma2(m2, NI25, a2);
            float cA, cB; unpack2(cov2, cA, cB);
            oA[(long)sl * C_DIM]          = cA;
            oA[(long)sl * C_DIM + HALF_C] = cB;
            if (sl + 1 < S_TILE) {
                const int r = sl + W, k = sl % W;
                u64 x2 = pack2(sx[r][iA], sx[r][iB]);
                u64 y2 = pack2(sx[r][jA], sx[r][jB]);
                u64 po = mul2(xr[k], yr[k]);  // outgoing product (bit-identical recompute)
                u64 p2 = mul2(x2, y2);
                s2p = add2(s2p, sub2(p2, po));
                s2x = add2(s2x, sub2(x2, xr[k]));
                s2y = add2(s2y, sub2(y2, yr[k]));
                xr[k] = x2; yr[k] = y2;
            }
        }
    } else {
        // ---- Tail tile (s_cnt = 28) ----
        #pragma unroll
        for (int sl = 0; sl < S_TILE; ++sl) {
            if (sl < s_cnt) {
                u64 m2   = mul2(s2x, s2y);
                u64 a2   = mul2(s2p, INVP);
                u64 cov2 = fma2(m2, NI25, a2);
                float cA, cB; unpack2(cov2, cA, cB);
                oA[(long)sl * C_DIM]          = cA;
                oA[(long)sl * C_DIM + HALF_C] = cB;
            }
            if (sl + 1 < s_cnt) {
                const int r = sl + W, k = sl % W;
                u64 x2 = pack2(sx[r][iA], sx[r][iB]);
                u64 y2 = pack2(sx[r][jA], sx[r][jB]);
                u64 po = mul2(xr[k], yr[k]);
                u64 p2 = mul2(x2, y2);
                s2p = add2(s2p, sub2(p2, po));
                s2x = add2(s2x, sub2(x2, xr[k]));
                s2y = add2(s2y, sub2(y2, yr[k]));
                xr[k] = x2; yr[k] = y2;
            }
        }
    }
}

extern "C" void kernel_launch(void* const* d_in, const int* in_sizes, int n_in,
                              void* d_out, int out_size) {
    const float* x = (const float*)d_in[0];
    float* out = (float*)d_out;
    (void)in_sizes; (void)n_in; (void)out_size;
    dim3 grid(TILES_PER_B, B_DIM);
    ts_cov_kernel<<<grid, NTHREADS>>>(x, out);
}